// round 16
// baseline (speedup 1.0000x reference)
#include <cuda_runtime.h>
#include <cuda_fp16.h>
#include <cstdint>

// ---------------------------------------------------------------------------
// GraphNeuralNetwork: 4 sparse layers, DEG=64 parents per node, B=512.
// Round 16: R14 structure (direct-L2 gather, 4-warp edge split, CTA=1 node,
// fp16 staging, fp32 weights+accum) + fma.rn.f32x2 packed MACs (bit-identical
// fp32 math, ~20% fewer issue slots in the inner loop). R15's fp16
// accumulation reverted (rel_err 9.5e-4, slower).
// ---------------------------------------------------------------------------

#define BATCH 512

__device__ __align__(16) __half g_hA[2048 * 512];
__device__ __align__(16) __half g_hB[2048 * 512];
__device__ __align__(16) int4   g_pairs[4][2048 * 32];  // {off0, w0, off1, w1} per edge pair

// ---------------------------------------------------------------------------
// Fused prep: transpose x (blocks 0..255) + pack edge pairs for all layers.
// offset = src * 1024 (byte offset of row in fp16 [node,batch] buffer).
// ---------------------------------------------------------------------------
__device__ __forceinline__ void prep_node_pairs(
    const int* __restrict__ src, const float* __restrict__ w,
    int gw, int lane, int4* __restrict__ ed) {
    int i0 = gw * 64 + 2 * lane;
    int   s0 = src[i0],     s1 = src[i0 + 1];
    float v0 = w[i0];       float v1 = w[i0 + 1];
    ed[gw * 32 + lane] = make_int4(s0 << 10, __float_as_int(v0),
                                   s1 << 10, __float_as_int(v1));
}

__global__ void fused_prep(
    const float* __restrict__ x, __half* __restrict__ hA,
    const int* __restrict__ src0, const float* __restrict__ w0,
    const int* __restrict__ src1, const float* __restrict__ w1,
    const int* __restrict__ src2, const float* __restrict__ w2,
    const int* __restrict__ src3, const float* __restrict__ w3,
    int4* __restrict__ ed) {
    __shared__ float t[32][33];
    int b   = blockIdx.x;
    int tid = threadIdx.x;

    if (b < 256) {
        // transpose x [512,512] fp32 -> hA [node, batch] fp16
        int bx = (b & 15) * 32, by = (b >> 4) * 32;
        int tx = tid & 31, ty = tid >> 5;       // 32 x 8
#pragma unroll
        for (int i = 0; i < 32; i += 8)
            t[ty + i][tx] = x[(by + ty + i) * 512 + bx + tx];
        __syncthreads();
#pragma unroll
        for (int i = 0; i < 32; i += 8)
            hA[(bx + ty + i) * 512 + by + tx] = __float2half(t[tx][ty + i]);
        return;
    }

    int lane = tid & 31;
    int warp = tid >> 5;                        // 8 warps/block -> 8 nodes/block
    int pb   = b - 256;
    if (pb < 256) {
        prep_node_pairs(src0, w0, pb * 8 + warp, lane, ed);
    } else if (pb < 512) {
        prep_node_pairs(src1, w1, (pb - 256) * 8 + warp, lane, ed + 1 * 2048 * 32);
    } else if (pb < 768) {
        prep_node_pairs(src2, w2, (pb - 512) * 8 + warp, lane, ed + 2 * 2048 * 32);
    } else {  // 64 blocks x 8 warps = 512 nodes
        prep_node_pairs(src3, w3, (pb - 768) * 8 + warp, lane, ed + 3 * 2048 * 32);
    }
}

// ---------------------------------------------------------------------------
// Direct-gather layer kernel, 4-warp split. CTA = 1 node, 8 warps:
//   warp w: grp = w>>2 (256-col half of batch), half = w&3 (16-edge quarter).
// Each warp gathers 16 edges (8 pair records) with coalesced LDG.128;
// MACs are packed fma.rn.f32x2 (fp32 math, half the FMA issue slots).
// Halves 1-3 publish partials to SMEM; half 0 combines, + bias, writes.
// ---------------------------------------------------------------------------
template <bool RELU, bool FINAL>
__global__ __launch_bounds__(256)
void layer_direct(const __half* __restrict__ h_in,
                  const int4*  __restrict__ pairs,
                  const float* __restrict__ bias,
                  void*        __restrict__ outv) {
    __shared__ float sPart[2][3][256];          // [grp][half-1][i*32 + lane]

    const int tid   = threadIdx.x;
    const int lane  = tid & 31;
    const int wInB  = tid >> 5;                 // 0..7
    const int half  = wInB & 3;
    const int grp   = wInB >> 2;                // 0/1
    const int node  = blockIdx.x;

    // byte base: col = grp*256 + lane*8 (fp16) -> bytes = grp*512 + lane*16
    const char* hb = (const char*)h_in + grp * 512 + lane * 16;
    const int4* ep = pairs + node * 32 + half * 8;

    // packed f32x2 accumulators: cols (lane*8 + 2i, +2i+1)
    unsigned long long A0 = 0ull, A1 = 0ull, A2 = 0ull, A3 = 0ull;

#pragma unroll
    for (int k = 0; k < 8; k++) {
        int4 e = __ldg(ep + k);
        uint4 g0 = __ldg((const uint4*)(hb + e.x));   // 8 cols of source row 0
        uint4 g1 = __ldg((const uint4*)(hb + e.z));   // 8 cols of source row 1
        unsigned long long w0p, w1p;
        asm("mov.b64 %0, {%1, %1};" : "=l"(w0p) : "r"(e.y));
        asm("mov.b64 %0, {%1, %1};" : "=l"(w1p) : "r"(e.w));

        float2 t; unsigned long long p;
#define ACC(G, W, A) \
        t = __half22float2(*(__half2*)&(G)); \
        asm("mov.b64 %0, {%1, %2};" : "=l"(p) : "f"(t.x), "f"(t.y)); \
        asm("fma.rn.f32x2 %0, %1, %2, %0;" : "+l"(A) : "l"(p), "l"(W));

        ACC(g0.x, w0p, A0) ACC(g0.y, w0p, A1) ACC(g0.z, w0p, A2) ACC(g0.w, w0p, A3)
        ACC(g1.x, w1p, A0) ACC(g1.y, w1p, A1) ACC(g1.z, w1p, A2) ACC(g1.w, w1p, A3)
#undef ACC
    }

    float a0 = __uint_as_float((unsigned)(A0      ));
    float a1 = __uint_as_float((unsigned)(A0 >> 32));
    float a2 = __uint_as_float((unsigned)(A1      ));
    float a3 = __uint_as_float((unsigned)(A1 >> 32));
    float a4 = __uint_as_float((unsigned)(A2      ));
    float a5 = __uint_as_float((unsigned)(A2 >> 32));
    float a6 = __uint_as_float((unsigned)(A3      ));
    float a7 = __uint_as_float((unsigned)(A3 >> 32));

    if (half != 0) {                            // warps 1-3 of each grp: publish
        float* sp = sPart[grp][half - 1];
        sp[0 * 32 + lane] = a0;
        sp[1 * 32 + lane] = a1;
        sp[2 * 32 + lane] = a2;
        sp[3 * 32 + lane] = a3;
        sp[4 * 32 + lane] = a4;
        sp[5 * 32 + lane] = a5;
        sp[6 * 32 + lane] = a6;
        sp[7 * 32 + lane] = a7;
    }
    __syncthreads();
    if (half != 0) return;

#pragma unroll
    for (int h = 0; h < 3; h++) {
        const float* sp = sPart[grp][h];
        a0 += sp[0 * 32 + lane];
        a1 += sp[1 * 32 + lane];
        a2 += sp[2 * 32 + lane];
        a3 += sp[3 * 32 + lane];
        a4 += sp[4 * 32 + lane];
        a5 += sp[5 * 32 + lane];
        a6 += sp[6 * 32 + lane];
        a7 += sp[7 * 32 + lane];
    }

    float bv = bias[node];
    float v0 = a0 + bv, v1 = a1 + bv, v2 = a2 + bv, v3 = a3 + bv;
    float v4 = a4 + bv, v5 = a5 + bv, v6 = a6 + bv, v7 = a7 + bv;
    if (RELU) {
        v0 = fmaxf(v0, 0.f); v1 = fmaxf(v1, 0.f); v2 = fmaxf(v2, 0.f); v3 = fmaxf(v3, 0.f);
        v4 = fmaxf(v4, 0.f); v5 = fmaxf(v5, 0.f); v6 = fmaxf(v6, 0.f); v7 = fmaxf(v7, 0.f);
    }

    if (!FINAL) {
        __half2 h0 = __floats2half2_rn(v0, v1);
        __half2 h1 = __floats2half2_rn(v2, v3);
        __half2 h2 = __floats2half2_rn(v4, v5);
        __half2 h3 = __floats2half2_rn(v6, v7);
        uint4 pk = make_uint4(*(unsigned*)&h0, *(unsigned*)&h1,
                              *(unsigned*)&h2, *(unsigned*)&h3);
        __half* out = (__half*)outv;
        *(uint4*)(out + (size_t)node * BATCH + grp * 256 + lane * 8) = pk;
    } else {
        // d_out [B, 512] fp32 row-major: out[col * 512 + node]
        float* out = (float*)outv;
        int c = grp * 256 + lane * 8;
        out[(size_t)(c + 0) * 512 + node] = v0;
        out[(size_t)(c + 1) * 512 + node] = v1;
        out[(size_t)(c + 2) * 512 + node] = v2;
        out[(size_t)(c + 3) * 512 + node] = v3;
        out[(size_t)(c + 4) * 512 + node] = v4;
        out[(size_t)(c + 5) * 512 + node] = v5;
        out[(size_t)(c + 6) * 512 + node] = v6;
        out[(size_t)(c + 7) * 512 + node] = v7;
    }
}

// ---------------------------------------------------------------------------
// Host launch
// ---------------------------------------------------------------------------
extern "C" void kernel_launch(void* const* d_in, const int* in_sizes, int n_in,
                              void* d_out, int out_size) {
    (void)n_in; (void)out_size;

    const float* x;
    const float* w[4];
    const float* b[4];
    const int*   src[4];

    if (in_sizes[0] == 2048) {
        // alphabetical metadata order: b0..b3, dst0..dst3, src0..src3, w0..w3, x
        for (int l = 0; l < 4; l++) {
            b[l]   = (const float*)d_in[l];
            src[l] = (const int*)d_in[8 + l];
            w[l]   = (const float*)d_in[12 + l];
        }
        x = (const float*)d_in[16];
    } else if (in_sizes[7] == 32768) {
        // reference-signature order: x, w0,b0, ..., w3,b3, src0,dst0, ...
        x = (const float*)d_in[0];
        for (int l = 0; l < 4; l++) {
            w[l]   = (const float*)d_in[1 + 2 * l];
            b[l]   = (const float*)d_in[2 + 2 * l];
            src[l] = (const int*)d_in[9 + 2 * l];
        }
    } else {
        // setup_inputs dict order: x, (w,b,src,dst) per layer
        x = (const float*)d_in[0];
        for (int l = 0; l < 4; l++) {
            w[l]   = (const float*)d_in[1 + 4 * l];
            b[l]   = (const float*)d_in[2 + 4 * l];
            src[l] = (const int*)d_in[3 + 4 * l];
        }
    }

    __half* hA; __half* hB; int4* ed;
    cudaGetSymbolAddress((void**)&hA, g_hA);
    cudaGetSymbolAddress((void**)&hB, g_hB);
    cudaGetSymbolAddress((void**)&ed, g_pairs);

    // 1) fused: transpose x -> hA (fp16) + pack edge pairs for all layers
    fused_prep<<<1088, 256>>>(x, hA,
                              src[0], w[0], src[1], w[1],
                              src[2], w[2], src[3], w[3],
                              ed);

    // 2) layers. CTA = 1 node (8 warps: 2 col-groups x 4 edge-quarters).
    layer_direct<true, false><<<2048, 256>>>(hA, ed + 0 * 2048 * 32, b[0], hB);
    layer_direct<true, false><<<2048, 256>>>(hB, ed + 1 * 2048 * 32, b[1], hA);
    layer_direct<true, false><<<2048, 256>>>(hA, ed + 2 * 2048 * 32, b[2], hB);
    layer_direct<false, true><<<512, 256>>>(hB, ed + 3 * 2048 * 32, b[3], d_out);
}

// round 17
// speedup vs baseline: 1.0539x; 1.0539x over previous
#include <cuda_runtime.h>
#include <cuda_fp16.h>
#include <cstdint>

// ---------------------------------------------------------------------------
// GraphNeuralNetwork: 4 sparse layers, DEG=64 parents per node, B=512.
// Round 17: hybrid of measured bests. Direct-L2 gather, fp16 staging,
// fp32 weights+accum, plain fmaf inner loop (R14 form; f32x2 and fp16-accum
// variants both measured slower / out of budget and reverted).
//   layers 1-2: 2-warp edge split (R13 shape, 16 pairs/warp, grid 1024)
//   layer 0 + final: 4-warp edge split (R14 shape, 8 pairs/warp)
// ---------------------------------------------------------------------------

#define BATCH 512

__device__ __align__(16) __half g_hA[2048 * 512];
__device__ __align__(16) __half g_hB[2048 * 512];
__device__ __align__(16) int4   g_pairs[4][2048 * 32];  // {off0, w0, off1, w1} per edge pair

// ---------------------------------------------------------------------------
// Fused prep: transpose x (blocks 0..255) + pack edge pairs for all layers.
// offset = src * 1024 (byte offset of row in fp16 [node,batch] buffer).
// ---------------------------------------------------------------------------
__device__ __forceinline__ void prep_node_pairs(
    const int* __restrict__ src, const float* __restrict__ w,
    int gw, int lane, int4* __restrict__ ed) {
    int i0 = gw * 64 + 2 * lane;
    int   s0 = src[i0],     s1 = src[i0 + 1];
    float v0 = w[i0];       float v1 = w[i0 + 1];
    ed[gw * 32 + lane] = make_int4(s0 << 10, __float_as_int(v0),
                                   s1 << 10, __float_as_int(v1));
}

__global__ void fused_prep(
    const float* __restrict__ x, __half* __restrict__ hA,
    const int* __restrict__ src0, const float* __restrict__ w0,
    const int* __restrict__ src1, const float* __restrict__ w1,
    const int* __restrict__ src2, const float* __restrict__ w2,
    const int* __restrict__ src3, const float* __restrict__ w3,
    int4* __restrict__ ed) {
    __shared__ float t[32][33];
    int b   = blockIdx.x;
    int tid = threadIdx.x;

    if (b < 256) {
        // transpose x [512,512] fp32 -> hA [node, batch] fp16
        int bx = (b & 15) * 32, by = (b >> 4) * 32;
        int tx = tid & 31, ty = tid >> 5;       // 32 x 8
#pragma unroll
        for (int i = 0; i < 32; i += 8)
            t[ty + i][tx] = x[(by + ty + i) * 512 + bx + tx];
        __syncthreads();
#pragma unroll
        for (int i = 0; i < 32; i += 8)
            hA[(bx + ty + i) * 512 + by + tx] = __float2half(t[tx][ty + i]);
        return;
    }

    int lane = tid & 31;
    int warp = tid >> 5;                        // 8 warps/block -> 8 nodes/block
    int pb   = b - 256;
    if (pb < 256) {
        prep_node_pairs(src0, w0, pb * 8 + warp, lane, ed);
    } else if (pb < 512) {
        prep_node_pairs(src1, w1, (pb - 256) * 8 + warp, lane, ed + 1 * 2048 * 32);
    } else if (pb < 768) {
        prep_node_pairs(src2, w2, (pb - 512) * 8 + warp, lane, ed + 2 * 2048 * 32);
    } else {  // 64 blocks x 8 warps = 512 nodes
        prep_node_pairs(src3, w3, (pb - 768) * 8 + warp, lane, ed + 3 * 2048 * 32);
    }
}

// ---------------------------------------------------------------------------
// Shared inner step: one edge pair -> 8 fp32 accumulators (lane covers 8 cols).
// ---------------------------------------------------------------------------
struct Acc8 { float a0, a1, a2, a3, a4, a5, a6, a7; };

__device__ __forceinline__ void acc_pair(const char* hb, int4 e, Acc8& A) {
    uint4 g0 = __ldg((const uint4*)(hb + e.x));   // 8 cols of source row 0
    uint4 g1 = __ldg((const uint4*)(hb + e.z));   // 8 cols of source row 1
    float w0 = __int_as_float(e.y);
    float w1 = __int_as_float(e.w);
    float2 t;
    t = __half22float2(*(__half2*)&g0.x); A.a0 = fmaf(t.x, w0, A.a0); A.a1 = fmaf(t.y, w0, A.a1);
    t = __half22float2(*(__half2*)&g0.y); A.a2 = fmaf(t.x, w0, A.a2); A.a3 = fmaf(t.y, w0, A.a3);
    t = __half22float2(*(__half2*)&g0.z); A.a4 = fmaf(t.x, w0, A.a4); A.a5 = fmaf(t.y, w0, A.a5);
    t = __half22float2(*(__half2*)&g0.w); A.a6 = fmaf(t.x, w0, A.a6); A.a7 = fmaf(t.y, w0, A.a7);
    t = __half22float2(*(__half2*)&g1.x); A.a0 = fmaf(t.x, w1, A.a0); A.a1 = fmaf(t.y, w1, A.a1);
    t = __half22float2(*(__half2*)&g1.y); A.a2 = fmaf(t.x, w1, A.a2); A.a3 = fmaf(t.y, w1, A.a3);
    t = __half22float2(*(__half2*)&g1.z); A.a4 = fmaf(t.x, w1, A.a4); A.a5 = fmaf(t.y, w1, A.a5);
    t = __half22float2(*(__half2*)&g1.w); A.a6 = fmaf(t.x, w1, A.a6); A.a7 = fmaf(t.y, w1, A.a7);
}

__device__ __forceinline__ void finish_write(
    float a0, float a1, float a2, float a3,
    float a4, float a5, float a6, float a7,
    const float* __restrict__ bias, void* __restrict__ outv,
    int node, int grp, int lane, bool relu, bool fin) {
    float bv = bias[node];
    float v0 = a0 + bv, v1 = a1 + bv, v2 = a2 + bv, v3 = a3 + bv;
    float v4 = a4 + bv, v5 = a5 + bv, v6 = a6 + bv, v7 = a7 + bv;
    if (relu) {
        v0 = fmaxf(v0, 0.f); v1 = fmaxf(v1, 0.f); v2 = fmaxf(v2, 0.f); v3 = fmaxf(v3, 0.f);
        v4 = fmaxf(v4, 0.f); v5 = fmaxf(v5, 0.f); v6 = fmaxf(v6, 0.f); v7 = fmaxf(v7, 0.f);
    }
    if (!fin) {
        __half2 h0 = __floats2half2_rn(v0, v1);
        __half2 h1 = __floats2half2_rn(v2, v3);
        __half2 h2 = __floats2half2_rn(v4, v5);
        __half2 h3 = __floats2half2_rn(v6, v7);
        uint4 pk = make_uint4(*(unsigned*)&h0, *(unsigned*)&h1,
                              *(unsigned*)&h2, *(unsigned*)&h3);
        __half* out = (__half*)outv;
        *(uint4*)(out + (size_t)node * BATCH + grp * 256 + lane * 8) = pk;
    } else {
        float* out = (float*)outv;              // d_out [B, 512] fp32 row-major
        int c = grp * 256 + lane * 8;
        out[(size_t)(c + 0) * 512 + node] = v0;
        out[(size_t)(c + 1) * 512 + node] = v1;
        out[(size_t)(c + 2) * 512 + node] = v2;
        out[(size_t)(c + 3) * 512 + node] = v3;
        out[(size_t)(c + 4) * 512 + node] = v4;
        out[(size_t)(c + 5) * 512 + node] = v5;
        out[(size_t)(c + 6) * 512 + node] = v6;
        out[(size_t)(c + 7) * 512 + node] = v7;
    }
}

// ---------------------------------------------------------------------------
// 2-warp split (layers 1-2). Warp wg: node = wg>>2, grp = (wg>>1)&1,
// half = wg&1 (32 edges = 16 pairs). Grid = nodes/2, 256 threads.
// ---------------------------------------------------------------------------
template <bool RELU, bool FINAL>
__global__ __launch_bounds__(256)
void layer_split2(const __half* __restrict__ h_in,
                  const int4*  __restrict__ pairs,
                  const float* __restrict__ bias,
                  void*        __restrict__ outv) {
    __shared__ float sPart[4][256];             // [unit][i*32 + lane]

    const int tid   = threadIdx.x;
    const int lane  = tid & 31;
    const int wInB  = tid >> 5;
    const int wg    = blockIdx.x * 8 + wInB;
    const int half  = wg & 1;
    const int grp   = (wg >> 1) & 1;
    const int node  = wg >> 2;
    const int unit  = wInB >> 1;

    const char* hb = (const char*)h_in + grp * 512 + lane * 16;
    const int4* ep = pairs + node * 32 + half * 16;

    Acc8 A = {0.f, 0.f, 0.f, 0.f, 0.f, 0.f, 0.f, 0.f};
#pragma unroll
    for (int k = 0; k < 16; k++)
        acc_pair(hb, __ldg(ep + k), A);

    if (half == 1) {
        float* sp = sPart[unit];
        sp[0 * 32 + lane] = A.a0; sp[1 * 32 + lane] = A.a1;
        sp[2 * 32 + lane] = A.a2; sp[3 * 32 + lane] = A.a3;
        sp[4 * 32 + lane] = A.a4; sp[5 * 32 + lane] = A.a5;
        sp[6 * 32 + lane] = A.a6; sp[7 * 32 + lane] = A.a7;
    }
    __syncthreads();
    if (half == 1) return;

    const float* sp = sPart[unit];
    finish_write(A.a0 + sp[0 * 32 + lane], A.a1 + sp[1 * 32 + lane],
                 A.a2 + sp[2 * 32 + lane], A.a3 + sp[3 * 32 + lane],
                 A.a4 + sp[4 * 32 + lane], A.a5 + sp[5 * 32 + lane],
                 A.a6 + sp[6 * 32 + lane], A.a7 + sp[7 * 32 + lane],
                 bias, outv, node, grp, lane, RELU, FINAL);
}

// ---------------------------------------------------------------------------
// 4-warp split (layer 0 + final). CTA = 1 node, 8 warps:
// grp = w>>2, half = w&3 (16 edges = 8 pairs). Grid = nodes.
// ---------------------------------------------------------------------------
template <bool RELU, bool FINAL>
__global__ __launch_bounds__(256)
void layer_split4(const __half* __restrict__ h_in,
                  const int4*  __restrict__ pairs,
                  const float* __restrict__ bias,
                  void*        __restrict__ outv) {
    __shared__ float sPart[2][3][256];          // [grp][half-1][i*32 + lane]

    const int tid   = threadIdx.x;
    const int lane  = tid & 31;
    const int wInB  = tid >> 5;
    const int half  = wInB & 3;
    const int grp   = wInB >> 2;
    const int node  = blockIdx.x;

    const char* hb = (const char*)h_in + grp * 512 + lane * 16;
    const int4* ep = pairs + node * 32 + half * 8;

    Acc8 A = {0.f, 0.f, 0.f, 0.f, 0.f, 0.f, 0.f, 0.f};
#pragma unroll
    for (int k = 0; k < 8; k++)
        acc_pair(hb, __ldg(ep + k), A);

    if (half != 0) {
        float* sp = sPart[grp][half - 1];
        sp[0 * 32 + lane] = A.a0; sp[1 * 32 + lane] = A.a1;
        sp[2 * 32 + lane] = A.a2; sp[3 * 32 + lane] = A.a3;
        sp[4 * 32 + lane] = A.a4; sp[5 * 32 + lane] = A.a5;
        sp[6 * 32 + lane] = A.a6; sp[7 * 32 + lane] = A.a7;
    }
    __syncthreads();
    if (half != 0) return;

#pragma unroll
    for (int h = 0; h < 3; h++) {
        const float* sp = sPart[grp][h];
        A.a0 += sp[0 * 32 + lane]; A.a1 += sp[1 * 32 + lane];
        A.a2 += sp[2 * 32 + lane]; A.a3 += sp[3 * 32 + lane];
        A.a4 += sp[4 * 32 + lane]; A.a5 += sp[5 * 32 + lane];
        A.a6 += sp[6 * 32 + lane]; A.a7 += sp[7 * 32 + lane];
    }
    finish_write(A.a0, A.a1, A.a2, A.a3, A.a4, A.a5, A.a6, A.a7,
                 bias, outv, node, grp, lane, RELU, FINAL);
}

// ---------------------------------------------------------------------------
// Host launch
// ---------------------------------------------------------------------------
extern "C" void kernel_launch(void* const* d_in, const int* in_sizes, int n_in,
                              void* d_out, int out_size) {
    (void)n_in; (void)out_size;

    const float* x;
    const float* w[4];
    const float* b[4];
    const int*   src[4];

    if (in_sizes[0] == 2048) {
        // alphabetical metadata order: b0..b3, dst0..dst3, src0..src3, w0..w3, x
        for (int l = 0; l < 4; l++) {
            b[l]   = (const float*)d_in[l];
            src[l] = (const int*)d_in[8 + l];
            w[l]   = (const float*)d_in[12 + l];
        }
        x = (const float*)d_in[16];
    } else if (in_sizes[7] == 32768) {
        // reference-signature order: x, w0,b0, ..., w3,b3, src0,dst0, ...
        x = (const float*)d_in[0];
        for (int l = 0; l < 4; l++) {
            w[l]   = (const float*)d_in[1 + 2 * l];
            b[l]   = (const float*)d_in[2 + 2 * l];
            src[l] = (const int*)d_in[9 + 2 * l];
        }
    } else {
        // setup_inputs dict order: x, (w,b,src,dst) per layer
        x = (const float*)d_in[0];
        for (int l = 0; l < 4; l++) {
            w[l]   = (const float*)d_in[1 + 4 * l];
            b[l]   = (const float*)d_in[2 + 4 * l];
            src[l] = (const int*)d_in[3 + 4 * l];
        }
    }

    __half* hA; __half* hB; int4* ed;
    cudaGetSymbolAddress((void**)&hA, g_hA);
    cudaGetSymbolAddress((void**)&hB, g_hB);
    cudaGetSymbolAddress((void**)&ed, g_pairs);

    // 1) fused: transpose x -> hA (fp16) + pack edge pairs for all layers
    fused_prep<<<1088, 256>>>(x, hA,
                              src[0], w[0], src[1], w[1],
                              src[2], w[2], src[3], w[3],
                              ed);

    // 2) layers (n_prev: 512, 2048, 2048, 2048)
    layer_split4<true, false><<<2048, 256>>>(hA, ed + 0 * 2048 * 32, b[0], hB);
    layer_split2<true, false><<<1024, 256>>>(hB, ed + 1 * 2048 * 32, b[1], hA);
    layer_split2<true, false><<<1024, 256>>>(hA, ed + 2 * 2048 * 32, b[2], hB);
    layer_split4<false, true><<<512, 256>>>(hB, ed + 3 * 2048 * 32, b[3], d_out);
}